// round 4
// baseline (speedup 1.0000x reference)
#include <cuda_runtime.h>
#include <cuda_bf16.h>
#include <cstdint>

// Problem constants
#define B_      32
#define C_      256
#define HW_     1024
#define NTOK    32768
#define KCODES  1024
#define BETA    0.25f

// Output layout (concatenated float32): u, z_train, vq_loss, indices
#define SZ_U    8388608
#define OFF_U   0
#define OFF_ZT  8388608
#define OFF_LOSS 16777216
#define OFF_IDX  16777217

// GEMM tiling
#define TOKT 256        // tokens per block
#define CODT 64         // codes per block
#define NTILE (KCODES / CODT)   // 16 code tiles
#define SA   264        // A smem stride (floats): %32 == 8 -> conflict-free frags
#define SB   36         // B smem stride (floats): %32 == 4 -> conflict-free frags

// Device scratch (static; no runtime allocation allowed)
__device__ float g_codebookT[C_ * KCODES];     // [c][code] for epilogue gather
__device__ float g_cnorm[KCODES];
__device__ float g_cmax;                       // max ||c||
__device__ float g_unorm[NTOK];                // ||u_tok||
__device__ int   g_idx[NTOK];
__device__ float g_partial[B_ * C_];
// per-(code-tile, token) argmin summaries
__device__ float g_t1v[NTILE * NTOK];
__device__ int   g_t1i[NTILE * NTOK];
__device__ float g_t2v[NTILE * NTOK];
// ambiguous-token worklist
__device__ int   g_nambig;
__device__ int   g_ambig[NTOK];

// ---------------------------------------------------------------------------
__device__ __forceinline__ uint32_t to_tf32(float f) {
    uint32_t r;
    asm("cvt.rna.tf32.f32 %0, %1;" : "=r"(r) : "f"(f));
    return r;
}

__device__ __forceinline__ void mma_tf32(float* c, const uint32_t* a,
                                         const uint32_t* b) {
    asm volatile(
        "mma.sync.aligned.m16n8k8.row.col.f32.tf32.tf32.f32 "
        "{%0,%1,%2,%3}, {%4,%5,%6,%7}, {%8,%9}, {%0,%1,%2,%3};"
        : "+f"(c[0]), "+f"(c[1]), "+f"(c[2]), "+f"(c[3])
        : "r"(a[0]), "r"(a[1]), "r"(a[2]), "r"(a[3]), "r"(b[0]), "r"(b[1]));
}

// update (m1,i1,m2) with a new (v, i); callers iterate i ascending
__device__ __forceinline__ void upd_min2(float v, int i, float& m1, int& i1,
                                         float& m2) {
    if (v < m1) { m2 = m1; m1 = v; i1 = i; }
    else if (v < m2) { m2 = v; }
}

// merge another (ov1, oi1, ov2) summary into (v1, i1, v2); ties -> lower index
__device__ __forceinline__ void merge_min2(float& v1, int& i1, float& v2,
                                           float ov1, int oi1, float ov2) {
    if (ov1 < v1 || (ov1 == v1 && oi1 < i1)) {
        v2 = fminf(v1, ov2);
        v1 = ov1; i1 = oi1;
    } else {
        v2 = fminf(v2, ov1);
    }
}

// ---------------------------------------------------------------------------
// K0: codebook prep: transpose to [c][code] + |c|^2; zero ambig counter
// ---------------------------------------------------------------------------
__global__ void __launch_bounds__(256) prep_kernel(const float* __restrict__ cb) {
    __shared__ float s[256];
    int k = blockIdx.x;
    int c = threadIdx.x;
    if (k == 0 && c == 0) g_nambig = 0;
    float v = cb[k * C_ + c];
    g_codebookT[c * KCODES + k] = v;
    s[c] = v * v;
    __syncthreads();
    #pragma unroll
    for (int stride = 128; stride > 0; stride >>= 1) {
        if (c < stride) s[c] += s[c + stride];
        __syncthreads();
    }
    if (c == 0) g_cnorm[k] = s[0];
}

// K0b: g_cmax = max ||c||
__global__ void __launch_bounds__(256) cmax_kernel() {
    __shared__ float s[256];
    int tid = threadIdx.x;
    float m = 0.f;
    for (int i = tid; i < KCODES; i += 256) m = fmaxf(m, g_cnorm[i]);
    s[tid] = m;
    __syncthreads();
    #pragma unroll
    for (int stride = 128; stride > 0; stride >>= 1) {
        if (tid < stride) s[tid] = fmaxf(s[tid], s[tid + stride]);
        __syncthreads();
    }
    if (tid == 0) g_cmax = sqrtf(s[0]) * 1.0002f;
}

// K0c: per-token ||u||
__global__ void __launch_bounds__(128) unorm_kernel(const float* __restrict__ u) {
    const int b = blockIdx.y;
    const int hw = blockIdx.x * 128 + threadIdx.x;
    const float* up = u + (size_t)b * (C_ * HW_) + hw;
    float acc = 0.f;
    #pragma unroll 8
    for (int c = 0; c < C_; ++c) {
        float v = up[c * HW_];
        acc = fmaf(v, v, acc);
    }
    g_unorm[(b << 10) + hw] = sqrtf(acc) * 1.0002f;
}

// ---------------------------------------------------------------------------
// K1: tf32 tensor GEMM with FUSED per-tile argmin.
// grid (16 code-tiles, 128 token-tiles), 256 threads (8 warps)
// ---------------------------------------------------------------------------
__global__ void __launch_bounds__(256) gemm_kernel(const float* __restrict__ u,
                                                   const float* __restrict__ cb) {
    __shared__ float As[32 * SA];   // [k][tok]  33 KB
    __shared__ float Bs[CODT * SB]; // [code][k]  9 KB

    const int tid = threadIdx.x;
    const int w = tid >> 5, lane = tid & 31;
    const int g = lane >> 2, q = lane & 3;
    const int code0 = blockIdx.x * CODT;
    const int tok0 = blockIdx.y * TOKT;
    const int b = tok0 >> 10, hw0 = tok0 & 1023;
    const float* ub = u + (size_t)b * (C_ * HW_) + hw0;

    float acc[2][8][4];
    #pragma unroll
    for (int m = 0; m < 2; ++m)
        #pragma unroll
        for (int j = 0; j < 8; ++j)
            #pragma unroll
            for (int e = 0; e < 4; ++e) acc[m][j][e] = 0.f;

    const uint32_t* Au = (const uint32_t*)As;
    const uint32_t* Bu = (const uint32_t*)Bs;

    for (int kc = 0; kc < 8; ++kc) {
        const int k0 = kc * 32;
        // stage A: 32 k-rows x 256 tokens, cvt to tf32. 2048 f4, 8/thread
        #pragma unroll
        for (int p = 0; p < 8; ++p) {
            int f = tid + p * 256;
            int kr = f >> 6, t4 = (f & 63) << 2;
            float4 v = *(const float4*)&ub[(size_t)(k0 + kr) * HW_ + t4];
            v.x = __uint_as_float(to_tf32(v.x));
            v.y = __uint_as_float(to_tf32(v.y));
            v.z = __uint_as_float(to_tf32(v.z));
            v.w = __uint_as_float(to_tf32(v.w));
            *(float4*)&As[kr * SA + t4] = v;
        }
        // stage B: 64 codes x 32 k. 512 f4, 2/thread
        #pragma unroll
        for (int p = 0; p < 2; ++p) {
            int f = tid + p * 256;
            int cr = f >> 3, k4 = (f & 7) << 2;
            float4 v = *(const float4*)&cb[(size_t)(code0 + cr) * C_ + k0 + k4];
            v.x = __uint_as_float(to_tf32(v.x));
            v.y = __uint_as_float(to_tf32(v.y));
            v.z = __uint_as_float(to_tf32(v.z));
            v.w = __uint_as_float(to_tf32(v.w));
            *(float4*)&Bs[cr * SB + k4] = v;
        }
        __syncthreads();

        #pragma unroll
        for (int ks = 0; ks < 4; ++ks) {
            const int kb = ks * 8;
            uint32_t bf[8][2];
            #pragma unroll
            for (int j = 0; j < 8; ++j) {
                int row = (j * 8 + g) * SB + kb + q;
                bf[j][0] = Bu[row];
                bf[j][1] = Bu[row + 4];
            }
            #pragma unroll
            for (int m = 0; m < 2; ++m) {
                const int arow = w * 32 + m * 16 + g;
                uint32_t af[4];
                af[0] = Au[(kb + q) * SA + arow];
                af[1] = Au[(kb + q) * SA + arow + 8];
                af[2] = Au[(kb + q + 4) * SA + arow];
                af[3] = Au[(kb + q + 4) * SA + arow + 8];
                #pragma unroll
                for (int j = 0; j < 8; ++j) mma_tf32(acc[m][j], af, bf[j]);
            }
        }
        __syncthreads();
    }

    // Fused epilogue: per-lane min1/min2 over this tile's 64 codes, then
    // merge across the 4 lanes of each quad (xor 1, xor 2).
    #pragma unroll
    for (int m = 0; m < 2; ++m) {
        float m1a = 3.4e38f, m2a = 3.4e38f; int i1a = 0;   // token t_lo
        float m1b = 3.4e38f, m2b = 3.4e38f; int i1b = 0;   // token t_lo + 8
        #pragma unroll
        for (int j = 0; j < 8; ++j) {
            const int col = code0 + j * 8 + q * 2;
            const float cn0 = __ldg(&g_cnorm[col]);
            const float cn1 = __ldg(&g_cnorm[col + 1]);
            upd_min2(fmaf(-2.f, acc[m][j][0], cn0), col,     m1a, i1a, m2a);
            upd_min2(fmaf(-2.f, acc[m][j][1], cn1), col + 1, m1a, i1a, m2a);
            upd_min2(fmaf(-2.f, acc[m][j][2], cn0), col,     m1b, i1b, m2b);
            upd_min2(fmaf(-2.f, acc[m][j][3], cn1), col + 1, m1b, i1b, m2b);
        }
        #pragma unroll
        for (int off = 1; off <= 2; off <<= 1) {
            float ov1 = __shfl_xor_sync(0xffffffffu, m1a, off);
            int   oi1 = __shfl_xor_sync(0xffffffffu, i1a, off);
            float ov2 = __shfl_xor_sync(0xffffffffu, m2a, off);
            merge_min2(m1a, i1a, m2a, ov1, oi1, ov2);
            ov1 = __shfl_xor_sync(0xffffffffu, m1b, off);
            oi1 = __shfl_xor_sync(0xffffffffu, i1b, off);
            ov2 = __shfl_xor_sync(0xffffffffu, m2b, off);
            merge_min2(m1b, i1b, m2b, ov1, oi1, ov2);
        }
        if (q == 0) {
            const int t_lo = tok0 + w * 32 + m * 16 + g;
            const size_t base = (size_t)blockIdx.x * NTOK;
            g_t1v[base + t_lo] = m1a;
            g_t1i[base + t_lo] = i1a;
            g_t2v[base + t_lo] = m2a;
            g_t1v[base + t_lo + 8] = m1b;
            g_t1i[base + t_lo + 8] = i1b;
            g_t2v[base + t_lo + 8] = m2b;
        }
    }
}

// ---------------------------------------------------------------------------
// K2: merge 16 tile summaries per token; margin check; build ambiguous list.
// ---------------------------------------------------------------------------
__global__ void __launch_bounds__(256) reduce_kernel(float* __restrict__ out_idx) {
    const int tok = blockIdx.x * 256 + threadIdx.x;
    float m1 = 3.4e38f, m2 = 3.4e38f;
    int i1 = 0;
    #pragma unroll
    for (int t = 0; t < NTILE; ++t) {
        const size_t p = (size_t)t * NTOK + tok;
        merge_min2(m1, i1, m2, g_t1v[p], g_t1i[p], g_t2v[p]);
    }
    g_idx[tok] = i1;
    out_idx[tok] = (float)i1;
    const float margin = g_unorm[tok] * g_cmax * (1.02f / 512.f) + 2e-3f;
    if (m2 - m1 <= margin) {
        int slot = atomicAdd(&g_nambig, 1);
        g_ambig[slot] = tok;
    }
}

// ---------------------------------------------------------------------------
// K3: exact fp32 rescue for ambiguous tokens. One warp per token,
// codes distributed across lanes; u staged in smem (broadcast reads).
// ---------------------------------------------------------------------------
__global__ void __launch_bounds__(256) rescue_kernel(const float* __restrict__ u,
                                                     const float* __restrict__ cb,
                                                     float* __restrict__ out_idx) {
    __shared__ float us[8][C_];
    const int wid = threadIdx.x >> 5, lane = threadIdx.x & 31;
    const int gw = blockIdx.x * 8 + wid;
    const int nwarps = gridDim.x * 8;
    const int n = g_nambig;

    for (int i = gw; i < n; i += nwarps) {
        const int tok = g_ambig[i];
        const int b = tok >> 10, hw = tok & 1023;
        #pragma unroll
        for (int r = 0; r < 8; ++r) {
            int c = lane + r * 32;
            us[wid][c] = u[((size_t)(b * C_ + c) << 10) + hw];
        }
        __syncwarp();
        float best = 3.4e38f;
        int bi = 0;
        for (int c0 = 0; c0 < KCODES; c0 += 32) {
            const int c = c0 + lane;
            const float* cp = cb + (size_t)c * C_;
            float dot = 0.f;
            #pragma unroll 8
            for (int k = 0; k < C_; ++k)
                dot = fmaf(us[wid][k], cp[k], dot);
            const float d = fmaf(-2.f, dot, g_cnorm[c]);
            if (d < best) { best = d; bi = c; }   // ascending c per lane
        }
        #pragma unroll
        for (int off = 16; off > 0; off >>= 1) {
            float ov = __shfl_xor_sync(0xffffffffu, best, off);
            int oi = __shfl_xor_sync(0xffffffffu, bi, off);
            if (ov < best || (ov == best && oi < bi)) { best = ov; bi = oi; }
        }
        if (lane == 0) {
            g_idx[tok] = bi;
            out_idx[tok] = (float)bi;
        }
        __syncwarp();
    }
}

// ---------------------------------------------------------------------------
// K4: outputs. copy u, gather z_q, accumulate (z_q - u)^2 per (b,c)
// ---------------------------------------------------------------------------
__global__ void __launch_bounds__(256) epilogue_kernel(const float* __restrict__ u,
                                                       float* __restrict__ out) {
    __shared__ float col[KCODES];
    __shared__ float sred[256];
    const int c = blockIdx.x;
    const int b = blockIdx.y;
    const int tid = threadIdx.x;

    ((float4*)col)[tid] = ((const float4*)(g_codebookT + c * KCODES))[tid];
    __syncthreads();

    const long base = ((long)(b * C_ + c)) << 10;
    const float* ub = u + base;
    float* ou = out + OFF_U + base;
    float* oz = out + OFF_ZT + base;
    const int* ib = g_idx + (b << 10);

    float acc = 0.f;
    #pragma unroll
    for (int j = 0; j < 4; ++j) {
        int hw = tid + (j << 8);
        int i = ib[hw];
        float z = col[i];
        float uu = ub[hw];
        ou[hw] = uu;
        oz[hw] = z;
        float d = z - uu;
        acc = fmaf(d, d, acc);
    }
    sred[tid] = acc;
    __syncthreads();
    #pragma unroll
    for (int stride = 128; stride > 0; stride >>= 1) {
        if (tid < stride) sred[tid] += sred[tid + stride];
        __syncthreads();
    }
    if (tid == 0) g_partial[b * C_ + c] = sred[0];
}

// ---------------------------------------------------------------------------
// K5: final loss. vq = (1 + BETA) * mean((z_q - u)^2)
// ---------------------------------------------------------------------------
__global__ void __launch_bounds__(256) loss_kernel(float* __restrict__ out) {
    __shared__ float s[256];
    const int tid = threadIdx.x;
    float a = 0.f;
    for (int i = tid; i < B_ * C_; i += 256) a += g_partial[i];
    s[tid] = a;
    __syncthreads();
    #pragma unroll
    for (int stride = 128; stride > 0; stride >>= 1) {
        if (tid < stride) s[tid] += s[tid + stride];
        __syncthreads();
    }
    if (tid == 0)
        out[OFF_LOSS] = s[0] * (1.0f + BETA) / (float)SZ_U;
}

// ---------------------------------------------------------------------------
extern "C" void kernel_launch(void* const* d_in, const int* in_sizes, int n_in,
                              void* d_out, int out_size) {
    const float* u  = (const float*)d_in[0];
    const float* cb = (const float*)d_in[1];
    float* out = (float*)d_out;

    prep_kernel<<<KCODES, 256>>>(cb);
    cmax_kernel<<<1, 256>>>();
    unorm_kernel<<<dim3(8, B_), 128>>>(u);
    gemm_kernel<<<dim3(NTILE, NTOK / TOKT), 256>>>(u, cb);
    reduce_kernel<<<NTOK / 256, 256>>>(out + OFF_IDX);
    rescue_kernel<<<256, 256>>>(u, cb, out + OFF_IDX);
    epilogue_kernel<<<dim3(C_, B_), 256>>>(u, out);
    loss_kernel<<<1, 256>>>(out);
}

// round 5
// speedup vs baseline: 5.5295x; 5.5295x over previous
#include <cuda_runtime.h>
#include <cuda_bf16.h>
#include <cstdint>

// Problem constants
#define B_      32
#define C_      256
#define HW_     1024
#define NTOK    32768
#define KCODES  1024
#define BETA    0.25f

// Output layout (concatenated float32): u, z_train, vq_loss, indices
#define SZ_U    8388608
#define OFF_U   0
#define OFF_ZT  8388608
#define OFF_LOSS 16777216
#define OFF_IDX  16777217

// GEMM tiling
#define TOKT 256
#define CODT 64
#define NTILE (KCODES / CODT)   // 16
#define SA   264        // A smem stride: %32==8 -> conflict-free frags
#define SB   36         // B smem stride: %32==4 -> conflict-free frags
#define MARGIN 1e-3f    // split-tf32 + fp32-accum pair bound (generous)

#define GEMM_SMEM ((64 * SA + 2 * 64 * SB) * 4)   // 86016 B

// Device scratch
__device__ float g_codebookT[C_ * KCODES];     // [c][code]
__device__ float g_cnorm[KCODES];
__device__ int   g_idx[NTOK];
__device__ float g_partial[B_ * C_];
__device__ float g_t1v[NTILE * NTOK];
__device__ int   g_t1i[NTILE * NTOK];
__device__ float g_t2v[NTILE * NTOK];
__device__ int   g_nambig;
__device__ int   g_ambig[NTOK];
__device__ float g_lim[NTOK];

// ---------------------------------------------------------------------------
__device__ __forceinline__ float to_tf32f(float f) {
    uint32_t r;
    asm("cvt.rna.tf32.f32 %0, %1;" : "=r"(r) : "f"(f));
    return __uint_as_float(r);
}

__device__ __forceinline__ void mma_tf32(float* c, const uint32_t* a,
                                         const uint32_t* b) {
    asm volatile(
        "mma.sync.aligned.m16n8k8.row.col.f32.tf32.tf32.f32 "
        "{%0,%1,%2,%3}, {%4,%5,%6,%7}, {%8,%9}, {%0,%1,%2,%3};"
        : "+f"(c[0]), "+f"(c[1]), "+f"(c[2]), "+f"(c[3])
        : "r"(a[0]), "r"(a[1]), "r"(a[2]), "r"(a[3]), "r"(b[0]), "r"(b[1]));
}

__device__ __forceinline__ void upd_min2(float v, int i, float& m1, int& i1,
                                         float& m2) {
    if (v < m1) { m2 = m1; m1 = v; i1 = i; }
    else if (v < m2) { m2 = v; }
}

__device__ __forceinline__ void merge_min2(float& v1, int& i1, float& v2,
                                           float ov1, int oi1, float ov2) {
    if (ov1 < v1 || (ov1 == v1 && oi1 < i1)) {
        v2 = fminf(v1, ov2);
        v1 = ov1; i1 = oi1;
    } else {
        v2 = fminf(v2, ov1);
    }
}

// ---------------------------------------------------------------------------
// K0: codebook transpose + |c|^2 + zero ambig counter
// ---------------------------------------------------------------------------
__global__ void __launch_bounds__(256) prep_kernel(const float* __restrict__ cb) {
    __shared__ float s[256];
    int k = blockIdx.x;
    int c = threadIdx.x;
    if (k == 0 && c == 0) g_nambig = 0;
    float v = cb[k * C_ + c];
    g_codebookT[c * KCODES + k] = v;
    s[c] = v * v;
    __syncthreads();
    #pragma unroll
    for (int stride = 128; stride > 0; stride >>= 1) {
        if (c < stride) s[c] += s[c + stride];
        __syncthreads();
    }
    if (c == 0) g_cnorm[k] = s[0];
}

// ---------------------------------------------------------------------------
// K1: split-tf32 tensor GEMM with fused per-tile argmin.
// dot = hi.hi + lo.hi + hi.lo  (error ~2^-21 ||u|| ||c||)
// grid (16 code-tiles, 128 token-tiles), 256 threads
// ---------------------------------------------------------------------------
__global__ void __launch_bounds__(256, 2) gemm_kernel(const float* __restrict__ u,
                                                      const float* __restrict__ cb) {
    extern __shared__ float sm[];
    float* Ah = sm;                    // [32][SA]
    float* Al = sm + 32 * SA;
    float* Bh = sm + 64 * SA;          // [64][SB]
    float* Bl = Bh + 64 * SB;

    const int tid = threadIdx.x;
    const int w = tid >> 5, lane = tid & 31;
    const int g = lane >> 2, q = lane & 3;
    const int code0 = blockIdx.x * CODT;
    const int tok0 = blockIdx.y * TOKT;
    const int b = tok0 >> 10, hw0 = tok0 & 1023;
    const float* ub = u + (size_t)b * (C_ * HW_) + hw0;

    float acc[2][8][4];
    #pragma unroll
    for (int m = 0; m < 2; ++m)
        #pragma unroll
        for (int j = 0; j < 8; ++j)
            #pragma unroll
            for (int e = 0; e < 4; ++e) acc[m][j][e] = 0.f;

    const uint32_t* Ahu = (const uint32_t*)Ah;
    const uint32_t* Alu = (const uint32_t*)Al;
    const uint32_t* Bhu = (const uint32_t*)Bh;
    const uint32_t* Blu = (const uint32_t*)Bl;

    for (int kc = 0; kc < 8; ++kc) {
        const int k0 = kc * 32;
        // stage A: 32 k-rows x 256 tokens -> hi/lo
        #pragma unroll
        for (int p = 0; p < 8; ++p) {
            int f = tid + p * 256;
            int kr = f >> 6, t4 = (f & 63) << 2;
            float4 v = *(const float4*)&ub[(size_t)(k0 + kr) * HW_ + t4];
            float4 h, l;
            h.x = to_tf32f(v.x); l.x = to_tf32f(v.x - h.x);
            h.y = to_tf32f(v.y); l.y = to_tf32f(v.y - h.y);
            h.z = to_tf32f(v.z); l.z = to_tf32f(v.z - h.z);
            h.w = to_tf32f(v.w); l.w = to_tf32f(v.w - h.w);
            *(float4*)&Ah[kr * SA + t4] = h;
            *(float4*)&Al[kr * SA + t4] = l;
        }
        // stage B: 64 codes x 32 k -> hi/lo
        #pragma unroll
        for (int p = 0; p < 2; ++p) {
            int f = tid + p * 256;
            int cr = f >> 3, k4 = (f & 7) << 2;
            float4 v = *(const float4*)&cb[(size_t)(code0 + cr) * C_ + k0 + k4];
            float4 h, l;
            h.x = to_tf32f(v.x); l.x = to_tf32f(v.x - h.x);
            h.y = to_tf32f(v.y); l.y = to_tf32f(v.y - h.y);
            h.z = to_tf32f(v.z); l.z = to_tf32f(v.z - h.z);
            h.w = to_tf32f(v.w); l.w = to_tf32f(v.w - h.w);
            *(float4*)&Bh[cr * SB + k4] = h;
            *(float4*)&Bl[cr * SB + k4] = l;
        }
        __syncthreads();

        #pragma unroll
        for (int ks = 0; ks < 4; ++ks) {
            const int kb = ks * 8;
            uint32_t bf[8][2];
            // pass 1+2: B hi with A hi and A lo
            #pragma unroll
            for (int j = 0; j < 8; ++j) {
                int row = (j * 8 + g) * SB + kb + q;
                bf[j][0] = Bhu[row];
                bf[j][1] = Bhu[row + 4];
            }
            #pragma unroll
            for (int m = 0; m < 2; ++m) {
                const int arow = w * 32 + m * 16 + g;
                uint32_t af[4];
                af[0] = Ahu[(kb + q) * SA + arow];
                af[1] = Ahu[(kb + q) * SA + arow + 8];
                af[2] = Ahu[(kb + q + 4) * SA + arow];
                af[3] = Ahu[(kb + q + 4) * SA + arow + 8];
                #pragma unroll
                for (int j = 0; j < 8; ++j) mma_tf32(acc[m][j], af, bf[j]);
                af[0] = Alu[(kb + q) * SA + arow];
                af[1] = Alu[(kb + q) * SA + arow + 8];
                af[2] = Alu[(kb + q + 4) * SA + arow];
                af[3] = Alu[(kb + q + 4) * SA + arow + 8];
                #pragma unroll
                for (int j = 0; j < 8; ++j) mma_tf32(acc[m][j], af, bf[j]);
            }
            // pass 3: B lo with A hi
            #pragma unroll
            for (int j = 0; j < 8; ++j) {
                int row = (j * 8 + g) * SB + kb + q;
                bf[j][0] = Blu[row];
                bf[j][1] = Blu[row + 4];
            }
            #pragma unroll
            for (int m = 0; m < 2; ++m) {
                const int arow = w * 32 + m * 16 + g;
                uint32_t af[4];
                af[0] = Ahu[(kb + q) * SA + arow];
                af[1] = Ahu[(kb + q) * SA + arow + 8];
                af[2] = Ahu[(kb + q + 4) * SA + arow];
                af[3] = Ahu[(kb + q + 4) * SA + arow + 8];
                #pragma unroll
                for (int j = 0; j < 8; ++j) mma_tf32(acc[m][j], af, bf[j]);
            }
        }
        __syncthreads();
    }

    // fused per-tile argmin epilogue
    #pragma unroll
    for (int m = 0; m < 2; ++m) {
        float m1a = 3.4e38f, m2a = 3.4e38f; int i1a = 0;
        float m1b = 3.4e38f, m2b = 3.4e38f; int i1b = 0;
        #pragma unroll
        for (int j = 0; j < 8; ++j) {
            const int col = code0 + j * 8 + q * 2;
            const float cn0 = __ldg(&g_cnorm[col]);
            const float cn1 = __ldg(&g_cnorm[col + 1]);
            upd_min2(fmaf(-2.f, acc[m][j][0], cn0), col,     m1a, i1a, m2a);
            upd_min2(fmaf(-2.f, acc[m][j][1], cn1), col + 1, m1a, i1a, m2a);
            upd_min2(fmaf(-2.f, acc[m][j][2], cn0), col,     m1b, i1b, m2b);
            upd_min2(fmaf(-2.f, acc[m][j][3], cn1), col + 1, m1b, i1b, m2b);
        }
        #pragma unroll
        for (int off = 1; off <= 2; off <<= 1) {
            float ov1 = __shfl_xor_sync(0xffffffffu, m1a, off);
            int   oi1 = __shfl_xor_sync(0xffffffffu, i1a, off);
            float ov2 = __shfl_xor_sync(0xffffffffu, m2a, off);
            merge_min2(m1a, i1a, m2a, ov1, oi1, ov2);
            ov1 = __shfl_xor_sync(0xffffffffu, m1b, off);
            oi1 = __shfl_xor_sync(0xffffffffu, i1b, off);
            ov2 = __shfl_xor_sync(0xffffffffu, m2b, off);
            merge_min2(m1b, i1b, m2b, ov1, oi1, ov2);
        }
        if (q == 0) {
            const int t_lo = tok0 + w * 32 + m * 16 + g;
            const size_t base = (size_t)blockIdx.x * NTOK;
            g_t1v[base + t_lo] = m1a;
            g_t1i[base + t_lo] = i1a;
            g_t2v[base + t_lo] = m2a;
            g_t1v[base + t_lo + 8] = m1b;
            g_t1i[base + t_lo + 8] = i1b;
            g_t2v[base + t_lo + 8] = m2b;
        }
    }
}

// ---------------------------------------------------------------------------
// K2: merge tile summaries; margin check; build ambiguous worklist.
// ---------------------------------------------------------------------------
__global__ void __launch_bounds__(256) reduce_kernel(float* __restrict__ out_idx) {
    const int tok = blockIdx.x * 256 + threadIdx.x;
    float m1 = 3.4e38f, m2 = 3.4e38f;
    int i1 = 0;
    #pragma unroll
    for (int t = 0; t < NTILE; ++t) {
        const size_t p = (size_t)t * NTOK + tok;
        merge_min2(m1, i1, m2, g_t1v[p], g_t1i[p], g_t2v[p]);
    }
    g_idx[tok] = i1;
    out_idx[tok] = (float)i1;
    if (m2 - m1 <= MARGIN) {
        int slot = atomicAdd(&g_nambig, 1);
        g_ambig[slot] = tok;
        g_lim[slot] = m1 + MARGIN;
    }
}

// ---------------------------------------------------------------------------
// K3: exact fp32 rescue, tile-filtered. Warp per token; only tiles whose
// tile-min is within the limit are rescanned. codebookT reads are coalesced.
// ---------------------------------------------------------------------------
__global__ void __launch_bounds__(256) rescue_kernel(const float* __restrict__ u,
                                                     float* __restrict__ out_idx) {
    __shared__ float us[8][C_];
    const int wid = threadIdx.x >> 5, lane = threadIdx.x & 31;
    const int gw = blockIdx.x * 8 + wid;
    const int nwarps = gridDim.x * 8;
    const int n = g_nambig;

    for (int i = gw; i < n; i += nwarps) {
        const int tok = g_ambig[i];
        const float lim = g_lim[i];
        const int b = tok >> 10, hw = tok & 1023;
        #pragma unroll
        for (int r = 0; r < 8; ++r) {
            int c = lane + r * 32;
            us[wid][c] = u[((size_t)(b * C_ + c) << 10) + hw];
        }
        __syncwarp();
        float best = 3.4e38f;
        int bi = KCODES;
        for (int t = 0; t < NTILE; ++t) {
            if (g_t1v[(size_t)t * NTOK + tok] > lim) continue;
            const int cb0 = t * CODT;
            const int c0 = cb0 + lane, c1 = cb0 + lane + 32;
            float d0 = 0.f, d1 = 0.f;
            #pragma unroll 8
            for (int k = 0; k < C_; ++k) {
                const float uv = us[wid][k];
                const float* row = g_codebookT + (size_t)k * KCODES + cb0;
                d0 = fmaf(uv, row[lane], d0);
                d1 = fmaf(uv, row[lane + 32], d1);
            }
            const float s0 = fmaf(-2.f, d0, g_cnorm[c0]);
            const float s1 = fmaf(-2.f, d1, g_cnorm[c1]);
            if (s0 < best || (s0 == best && c0 < bi)) { best = s0; bi = c0; }
            if (s1 < best || (s1 == best && c1 < bi)) { best = s1; bi = c1; }
        }
        #pragma unroll
        for (int off = 16; off > 0; off >>= 1) {
            float ov = __shfl_xor_sync(0xffffffffu, best, off);
            int oi = __shfl_xor_sync(0xffffffffu, bi, off);
            if (ov < best || (ov == best && oi < bi)) { best = ov; bi = oi; }
        }
        if (lane == 0) {
            g_idx[tok] = bi;
            out_idx[tok] = (float)bi;
        }
        __syncwarp();
    }
}

// ---------------------------------------------------------------------------
// K4: outputs. copy u, gather z_q, accumulate (z_q - u)^2 per (b,c)
// ---------------------------------------------------------------------------
__global__ void __launch_bounds__(256) epilogue_kernel(const float* __restrict__ u,
                                                       float* __restrict__ out) {
    __shared__ float col[KCODES];
    __shared__ float sred[256];
    const int c = blockIdx.x;
    const int b = blockIdx.y;
    const int tid = threadIdx.x;

    ((float4*)col)[tid] = ((const float4*)(g_codebookT + c * KCODES))[tid];
    __syncthreads();

    const long base = ((long)(b * C_ + c)) << 10;
    const float* ub = u + base;
    float* ou = out + OFF_U + base;
    float* oz = out + OFF_ZT + base;
    const int* ib = g_idx + (b << 10);

    float acc = 0.f;
    #pragma unroll
    for (int j = 0; j < 4; ++j) {
        int hw = tid + (j << 8);
        int i = ib[hw];
        float z = col[i];
        float uu = ub[hw];
        ou[hw] = uu;
        oz[hw] = z;
        float d = z - uu;
        acc = fmaf(d, d, acc);
    }
    sred[tid] = acc;
    __syncthreads();
    #pragma unroll
    for (int stride = 128; stride > 0; stride >>= 1) {
        if (tid < stride) sred[tid] += sred[tid + stride];
        __syncthreads();
    }
    if (tid == 0) g_partial[b * C_ + c] = sred[0];
}

// ---------------------------------------------------------------------------
// K5: final loss. vq = (1 + BETA) * mean((z_q - u)^2)
// ---------------------------------------------------------------------------
__global__ void __launch_bounds__(256) loss_kernel(float* __restrict__ out) {
    __shared__ float s[256];
    const int tid = threadIdx.x;
    float a = 0.f;
    for (int i = tid; i < B_ * C_; i += 256) a += g_partial[i];
    s[tid] = a;
    __syncthreads();
    #pragma unroll
    for (int stride = 128; stride > 0; stride >>= 1) {
        if (tid < stride) s[tid] += s[tid + stride];
        __syncthreads();
    }
    if (tid == 0)
        out[OFF_LOSS] = s[0] * (1.0f + BETA) / (float)SZ_U;
}

// ---------------------------------------------------------------------------
extern "C" void kernel_launch(void* const* d_in, const int* in_sizes, int n_in,
                              void* d_out, int out_size) {
    const float* u  = (const float*)d_in[0];
    const float* cb = (const float*)d_in[1];
    float* out = (float*)d_out;

    static bool attr_done = false;
    if (!attr_done) {
        cudaFuncSetAttribute(gemm_kernel,
                             cudaFuncAttributeMaxDynamicSharedMemorySize,
                             GEMM_SMEM);
        attr_done = true;
    }

    prep_kernel<<<KCODES, 256>>>(cb);
    gemm_kernel<<<dim3(NTILE, NTOK / TOKT), 256, GEMM_SMEM>>>(u, cb);
    reduce_kernel<<<NTOK / 256, 256>>>(out + OFF_IDX);
    rescue_kernel<<<128, 256>>>(u, out + OFF_IDX);
    epilogue_kernel<<<dim3(C_, B_), 256>>>(u, out);
    loss_kernel<<<1, 256>>>(out);
}